// round 5
// baseline (speedup 1.0000x reference)
#include <cuda_runtime.h>
#include <math.h>

#define BB 8
#define CC 64
#define OO 64
#define HH 128
#define WW 128
#define HWSZ (HH*WW)            // 16384
#define NPIX (BB*HWSZ)          // 131072
#define TPB 256

typedef unsigned long long ull;

// ---------------- scratch (allocation-free: __device__ globals) --------------
__device__ float  g_wom_t[CC*9*28];            // [c][t][j] j:0..17 offset,18..26 mask,27 pad
__device__ float  g_Wt[CC*576];                // [c][k*64+o]
__device__ float4 g_cw4[(size_t)NPIX*9];       // per (p,k): 4 corner weights (mask folded)
__device__ int4   g_ci4[(size_t)NPIX*9];       // per (p,k): 4 clamped hw indices
__device__ float  g_xt[(size_t)NPIX*CC];       // x transposed: [b][hw][c]  (33.5 MB)

// ---------------- packed f32x2 helpers ---------------------------------------
__device__ __forceinline__ ull pk2(float lo, float hi){
    ull r; asm("mov.b64 %0, {%1,%2};" : "=l"(r) : "f"(lo), "f"(hi)); return r;
}
__device__ __forceinline__ void upk2(ull v, float& lo, float& hi){
    asm("mov.b64 {%0,%1}, %2;" : "=f"(lo), "=f"(hi) : "l"(v));
}
__device__ __forceinline__ ull f2fma(ull a, ull b, ull c){
    ull d; asm("fma.rn.f32x2 %0, %1, %2, %3;" : "=l"(d) : "l"(a), "l"(b), "l"(c)); return d;
}
__device__ __forceinline__ ull ldg2(const float* p){
    ull v; asm("ld.global.nc.b64 %0, [%1];" : "=l"(v) : "l"(p)); return v;
}

// ---------------- prep: transpose weights ------------------------------------
__global__ void k_prep(const float* __restrict__ wm,
                       const float* __restrict__ wo,
                       const float* __restrict__ wk){
    int i = blockIdx.x*TPB + threadIdx.x;
    if (i < CC*576){                       // g_Wt[c][k*64+o] = wm[o,c,k]
        int c = i/576; int r = i - c*576; int k = r/64; int o = r - k*64;
        g_Wt[i] = wm[(o*CC + c)*9 + k];
    }
    int j2 = i - CC*576;
    if (j2 >= 0 && j2 < CC*9*28){
        int ct = j2/28; int j = j2 - ct*28; int c = ct/9; int t = ct - c*9;
        float v = 0.f;
        if (j < 18)      v = wo[(j*CC + c)*9 + t];
        else if (j < 27) v = wk[((j-18)*CC + c)*9 + t];
        g_wom_t[j2] = v;
    }
}

// ---------------- P0: x [b][c][hw] -> g_xt [b][hw][c] -------------------------
__global__ void k_xt(const float* __restrict__ x){
    __shared__ float t[32][33];
    int b  = blockIdx.z;
    int c0 = blockIdx.y*32;
    int hw0= blockIdx.x*32;
    const float* xb = x + ((size_t)b*CC + c0)*HWSZ + hw0;
    for (int i = threadIdx.y; i < 32; i += 8)
        t[i][threadIdx.x] = xb[(size_t)i*HWSZ + threadIdx.x];   // t[c][hw]
    __syncthreads();
    float* xtb = g_xt + ((size_t)b*HWSZ + hw0)*CC + c0;
    for (int i = threadIdx.y; i < 32; i += 8)
        xtb[(size_t)i*CC + threadIdx.x] = t[threadIdx.x][i];    // [hw][c]
}

// ---- P1: offset(18)+mask(9) 3x3 conv, fused; emit folded corner wgts/idx ----
__global__ void __launch_bounds__(TPB)
k_offmask(const float* __restrict__ x,
          const float* __restrict__ boff,
          const float* __restrict__ bmsk){
    __shared__ __align__(16) float s_wom[32*9*28];   // 31.5 KB

    int p   = blockIdx.x*TPB + threadIdx.x;
    int b   = p >> 14;
    int hw  = p & (HWSZ-1);
    int h   = hw >> 7;
    int wp  = hw & (WW-1);
    const float* xb = x + (size_t)b*CC*HWSZ;

    ull acc[14];
    #pragma unroll
    for (int q=0;q<14;q++){
        int j0=2*q, j1=2*q+1;
        float lo = (j0<18)? boff[j0] : (j0<27 ? bmsk[j0-18] : 0.f);
        float hi = (j1<18)? boff[j1] : (j1<27 ? bmsk[j1-18] : 0.f);
        acc[q] = pk2(lo,hi);
    }

    for (int cc=0; cc<CC; cc+=32){
        __syncthreads();
        for (int i=threadIdx.x; i<32*9*28; i+=TPB)
            s_wom[i] = g_wom_t[cc*9*28 + i];
        __syncthreads();

        for (int c=0;c<32;c++){
            const float* xc = xb + (cc+c)*HWSZ;
            float v[9];
            #pragma unroll
            for (int t=0;t<9;t++){
                int yy = h + t/3 - 1, xx = wp + t%3 - 1;
                v[t] = (yy>=0 && yy<HH && xx>=0 && xx<WW) ? __ldg(xc + yy*WW + xx) : 0.f;
            }
            #pragma unroll
            for (int t=0;t<9;t++){
                ull vv = pk2(v[t], v[t]);
                const ulonglong2* wq = (const ulonglong2*)&s_wom[(c*9+t)*28];
                #pragma unroll
                for (int q=0;q<7;q++){
                    ulonglong2 ww = wq[q];
                    acc[2*q]   = f2fma(vv, ww.x, acc[2*q]);
                    acc[2*q+1] = f2fma(vv, ww.y, acc[2*q+1]);
                }
            }
        }
    }

    // epilogue: fold sigmoid(mask) + bilinear validity into 4 corner weights
    #pragma unroll
    for (int k=0;k<9;k++){
        float dy, dx; upk2(acc[k], dy, dx);
        float mlo, mhi; upk2(acc[9 + k/2], mlo, mhi);
        float mraw = (k & 1) ? mhi : mlo;
        float mk = 1.f/(1.f + expf(-mraw));

        float py = dy + (float)(h + k/3 - 1);
        float px = dx + (float)(wp + k%3 - 1);
        float y0f = floorf(py), x0f = floorf(px);
        float ly = py - y0f, lx = px - x0f;
        int y0 = (int)y0f, x0 = (int)x0f;
        int y1 = y0 + 1,   x1 = x0 + 1;

        float vy0 = (y0>=0 && y0<HH) ? 1.f : 0.f;
        float vy1 = (y1>=0 && y1<HH) ? 1.f : 0.f;
        float vx0 = (x0>=0 && x0<WW) ? 1.f : 0.f;
        float vx1 = (x1>=0 && x1<WW) ? 1.f : 0.f;

        float w00 = (1.f-ly)*(1.f-lx)*vy0*vx0*mk;
        float w01 = (1.f-ly)*lx      *vy0*vx1*mk;
        float w10 = ly      *(1.f-lx)*vy1*vx0*mk;
        float w11 = ly      *lx      *vy1*vx1*mk;

        int y0c = min(max(y0,0),HH-1), y1c = min(max(y1,0),HH-1);
        int x0c = min(max(x0,0),WW-1), x1c = min(max(x1,0),WW-1);

        g_cw4[(size_t)p*9 + k] = make_float4(w00,w01,w10,w11);
        g_ci4[(size_t)p*9 + k] = make_int4(y0c*WW+x0c, y0c*WW+x1c,
                                           y1c*WW+x0c, y1c*WW+x1c);
    }
}

// ---- P2: fused warp-cooperative gather + GEMM --------------------------------
// CTA = 64 px. Per k: warp w gathers pixels [w*8, w*8+8) — all 32 lanes read the
// SAME 256B corner row of x_t (coalesced), fold the 4 bilinear+mask weights,
// STS.64 into A_px[px][c]. Then 64px x 64o x 64c GEMM chunk, acc packed over o.
__global__ void __launch_bounds__(TPB)
k_fused(float* __restrict__ out){
    __shared__ __align__(16) float A_px[64][68];   // [px][c], pad 68 (17x16B)
    __shared__ __align__(16) float B_s[64][64];    // [c][o]

    int t    = threadIdx.x;
    int w    = t >> 5;
    int l    = t & 31;
    int pblk = blockIdx.x;
    int b    = (pblk*64) >> 14;
    int hw0  = (pblk*64) & (HWSZ-1);
    const float* xtb = g_xt + (size_t)b*HWSZ*CC;

    // gemm roles: 8 o per thread (tx), 2 px per thread (ty)
    int tx = t & 7;         // o0 = tx*8
    int ty = t >> 3;        // px0 = ty*2
    int o0 = tx*8;

    // B-load role: c = t>>2, 16 floats along o
    int bc = t >> 2, bo = (t & 3)*16;

    // accumulate over k outside? No — out stored per CTA once; acc lives across k.
    ull acc[2][4];
    #pragma unroll
    for (int i=0;i<2;i++){ acc[i][0]=0ull; acc[i][1]=0ull; acc[i][2]=0ull; acc[i][3]=0ull; }

    for (int k=0;k<9;k++){
        __syncthreads();
        // load B slice for this k
        #pragma unroll
        for (int q=0;q<4;q++)
            *(float4*)&B_s[bc][bo+4*q] = *(const float4*)(g_Wt + bc*576 + k*64 + bo + 4*q);

        // warp-cooperative gather: 8 pixels per warp
        #pragma unroll
        for (int j=0;j<8;j++){
            int px = w*8 + j;
            size_t pk9 = (size_t)(pblk*64 + px)*9 + k;
            float4 wq = __ldg(&g_cw4[pk9]);
            int4   iq = __ldg(&g_ci4[pk9]);
            ull v;
            v = f2fma(pk2(wq.x,wq.x), ldg2(xtb + (size_t)iq.x*CC + 2*l), 0ull);
            v = f2fma(pk2(wq.y,wq.y), ldg2(xtb + (size_t)iq.y*CC + 2*l), v);
            v = f2fma(pk2(wq.z,wq.z), ldg2(xtb + (size_t)iq.z*CC + 2*l), v);
            v = f2fma(pk2(wq.w,wq.w), ldg2(xtb + (size_t)iq.w*CC + 2*l), v);
            *(ull*)&A_px[px][2*l] = v;     // STS.64, conflict-free row write
        }
        __syncthreads();

        // GEMM chunk: acc[px 2][o 8] += A_px[px][c] * B_s[c][o]
        #pragma unroll 8
        for (int kk=0; kk<64; kk++){
            float a0 = A_px[ty*2  ][kk];
            float a1 = A_px[ty*2+1][kk];
            ull av0 = pk2(a0,a0), av1 = pk2(a1,a1);
            ulonglong2 b01 = *(ulonglong2*)&B_s[kk][o0];
            ulonglong2 b23 = *(ulonglong2*)&B_s[kk][o0+4];
            acc[0][0]=f2fma(av0,b01.x,acc[0][0]); acc[0][1]=f2fma(av0,b01.y,acc[0][1]);
            acc[0][2]=f2fma(av0,b23.x,acc[0][2]); acc[0][3]=f2fma(av0,b23.y,acc[0][3]);
            acc[1][0]=f2fma(av1,b01.x,acc[1][0]); acc[1][1]=f2fma(av1,b01.y,acc[1][1]);
            acc[1][2]=f2fma(av1,b23.x,acc[1][2]); acc[1][3]=f2fma(av1,b23.y,acc[1][3]);
        }
    }

    // epilogue: direct scattered STG (32B-sector aligned groups)
    #pragma unroll
    for (int i=0;i<2;i++){
        int hw = hw0 + ty*2 + i;
        float* ob = out + (size_t)b*OO*HWSZ + hw;
        #pragma unroll
        for (int q=0;q<4;q++){
            float lo,hi; upk2(acc[i][q],lo,hi);
            ob[(size_t)(o0+2*q  )*HWSZ] = lo;
            ob[(size_t)(o0+2*q+1)*HWSZ] = hi;
        }
    }
}

// ---------------- launch ------------------------------------------------------
extern "C" void kernel_launch(void* const* d_in, const int* in_sizes, int n_in,
                              void* d_out, int out_size){
    const float* x        = (const float*)d_in[0];
    const float* w_main   = (const float*)d_in[1];
    const float* w_offset = (const float*)d_in[2];
    const float* b_offset = (const float*)d_in[3];
    const float* w_mask   = (const float*)d_in[4];
    const float* b_mask   = (const float*)d_in[5];
    float* out = (float*)d_out;

    int prep_n = CC*576 + CC*9*28;
    k_prep<<<(prep_n + TPB-1)/TPB, TPB>>>(w_main, w_offset, w_mask);
    dim3 gx(HWSZ/32, CC/32, BB);
    k_xt<<<gx, dim3(32,8)>>>(x);
    k_offmask<<<NPIX/TPB, TPB>>>(x, b_offset, b_mask);
    k_fused<<<NPIX/64, TPB>>>(out);
}

// round 6
// speedup vs baseline: 1.1609x; 1.1609x over previous
#include <cuda_runtime.h>
#include <math.h>

#define BB 8
#define CC 64
#define OO 64
#define HH 128
#define WW 128
#define HWSZ (HH*WW)            // 16384
#define NPIX (BB*HWSZ)          // 131072
#define TPB 256

typedef unsigned long long ull;

// ---------------- scratch (allocation-free: __device__ globals) --------------
__device__ float  g_wom_t[CC*9*28];            // [c][t][j] j:0..17 offset,18..26 mask,27 pad
__device__ float  g_Wt[CC*576];                // [c][k*64+o]
__device__ float4 g_cw4[(size_t)NPIX*9];       // per (p,k): 4 corner weights (mask folded)
__device__ int4   g_ci4[(size_t)NPIX*9];       // per (p,k): 4 clamped hw indices
__device__ float  g_Y[(size_t)9*HWSZ*OO];      // ONE batch: [k][hw][o]  (37.7 MB, L2-resident)

// ---------------- packed f32x2 helpers ---------------------------------------
__device__ __forceinline__ ull pk2(float lo, float hi){
    ull r; asm("mov.b64 %0, {%1,%2};" : "=l"(r) : "f"(lo), "f"(hi)); return r;
}
__device__ __forceinline__ void upk2(ull v, float& lo, float& hi){
    asm("mov.b64 {%0,%1}, %2;" : "=f"(lo), "=f"(hi) : "l"(v));
}
__device__ __forceinline__ ull f2fma(ull a, ull b, ull c){
    ull d; asm("fma.rn.f32x2 %0, %1, %2, %3;" : "=l"(d) : "l"(a), "l"(b), "l"(c)); return d;
}
__device__ __forceinline__ ull f2add(ull a, ull b){
    ull d; asm("add.rn.f32x2 %0, %1, %2;" : "=l"(d) : "l"(a), "l"(b)); return d;
}
__device__ __forceinline__ ull ldg2(const float* p){
    ull v; asm("ld.global.nc.b64 %0, [%1];" : "=l"(v) : "l"(p)); return v;
}

// ---------------- prep: transpose weights ------------------------------------
__global__ void k_prep(const float* __restrict__ wm,
                       const float* __restrict__ wo,
                       const float* __restrict__ wk){
    int i = blockIdx.x*TPB + threadIdx.x;
    if (i < CC*576){                       // g_Wt[c][k*64+o] = wm[o,c,k]
        int c = i/576; int r = i - c*576; int k = r/64; int o = r - k*64;
        g_Wt[i] = wm[(o*CC + c)*9 + k];
    }
    int j2 = i - CC*576;
    if (j2 >= 0 && j2 < CC*9*28){
        int ct = j2/28; int j = j2 - ct*28; int c = ct/9; int t = ct - c*9;
        float v = 0.f;
        if (j < 18)      v = wo[(j*CC + c)*9 + t];
        else if (j < 27) v = wk[((j-18)*CC + c)*9 + t];
        g_wom_t[j2] = v;
    }
}

// ---- P1: offset(18)+mask(9) 3x3 conv, fused; emit folded corner wgts/idx ----
__global__ void __launch_bounds__(TPB)
k_offmask(const float* __restrict__ x,
          const float* __restrict__ boff,
          const float* __restrict__ bmsk){
    __shared__ __align__(16) float s_wom[32*9*28];   // 31.5 KB

    int p   = blockIdx.x*TPB + threadIdx.x;
    int b   = p >> 14;
    int hw  = p & (HWSZ-1);
    int h   = hw >> 7;
    int wp  = hw & (WW-1);
    const float* xb = x + (size_t)b*CC*HWSZ;

    ull acc[14];
    #pragma unroll
    for (int q=0;q<14;q++){
        int j0=2*q, j1=2*q+1;
        float lo = (j0<18)? boff[j0] : (j0<27 ? bmsk[j0-18] : 0.f);
        float hi = (j1<18)? boff[j1] : (j1<27 ? bmsk[j1-18] : 0.f);
        acc[q] = pk2(lo,hi);
    }

    for (int cc=0; cc<CC; cc+=32){
        __syncthreads();
        for (int i=threadIdx.x; i<32*9*28; i+=TPB)
            s_wom[i] = g_wom_t[cc*9*28 + i];
        __syncthreads();

        for (int c=0;c<32;c++){
            const float* xc = xb + (cc+c)*HWSZ;
            float v[9];
            #pragma unroll
            for (int t=0;t<9;t++){
                int yy = h + t/3 - 1, xx = wp + t%3 - 1;
                v[t] = (yy>=0 && yy<HH && xx>=0 && xx<WW) ? __ldg(xc + yy*WW + xx) : 0.f;
            }
            #pragma unroll
            for (int t=0;t<9;t++){
                ull vv = pk2(v[t], v[t]);
                const ulonglong2* wq = (const ulonglong2*)&s_wom[(c*9+t)*28];
                #pragma unroll
                for (int q=0;q<7;q++){
                    ulonglong2 ww = wq[q];
                    acc[2*q]   = f2fma(vv, ww.x, acc[2*q]);
                    acc[2*q+1] = f2fma(vv, ww.y, acc[2*q+1]);
                }
            }
        }
    }

    // epilogue: fold sigmoid(mask) + bilinear validity into 4 corner weights
    #pragma unroll
    for (int k=0;k<9;k++){
        float dy, dx; upk2(acc[k], dy, dx);
        float mlo, mhi; upk2(acc[9 + k/2], mlo, mhi);
        float mraw = (k & 1) ? mhi : mlo;
        float mk = 1.f/(1.f + expf(-mraw));

        float py = dy + (float)(h + k/3 - 1);
        float px = dx + (float)(wp + k%3 - 1);
        float y0f = floorf(py), x0f = floorf(px);
        float ly = py - y0f, lx = px - x0f;
        int y0 = (int)y0f, x0 = (int)x0f;
        int y1 = y0 + 1,   x1 = x0 + 1;

        float vy0 = (y0>=0 && y0<HH) ? 1.f : 0.f;
        float vy1 = (y1>=0 && y1<HH) ? 1.f : 0.f;
        float vx0 = (x0>=0 && x0<WW) ? 1.f : 0.f;
        float vx1 = (x1>=0 && x1<WW) ? 1.f : 0.f;

        float w00 = (1.f-ly)*(1.f-lx)*vy0*vx0*mk;
        float w01 = (1.f-ly)*lx      *vy0*vx1*mk;
        float w10 = ly      *(1.f-lx)*vy1*vx0*mk;
        float w11 = ly      *lx      *vy1*vx1*mk;

        int y0c = min(max(y0,0),HH-1), y1c = min(max(y1,0),HH-1);
        int x0c = min(max(x0,0),WW-1), x1c = min(max(x1,0),WW-1);

        g_cw4[(size_t)p*9 + k] = make_float4(w00,w01,w10,w11);
        g_ci4[(size_t)p*9 + k] = make_int4(y0c*WW+x0c, y0c*WW+x1c,
                                           y1c*WW+x0c, y1c*WW+x1c);
    }
}

// ---- P2: per-batch GEMM  Y[k,hw,o] = sum_c x[b,c,hw] * Wt[c][k*64+o] --------
// CTA = 128 px tile of batch b, loops all 9 k (A loaded once). acc packed over px.
__global__ void __launch_bounds__(TPB)
k_gemm(const float* __restrict__ x, int b){
    __shared__ __align__(16) float A_s[64][128];   // 32 KB [c][px]
    __shared__ __align__(16) float B_s[64][64];    // 16 KB [c][o]

    int t    = threadIdx.x;
    int hw0  = blockIdx.x*128;
    const float* xb = x + (size_t)b*CC*HWSZ + hw0;

    #pragma unroll
    for (int i=t; i<64*32; i+=TPB){
        int c = i>>5, q4 = i&31;
        *(float4*)&A_s[c][q4*4] = __ldg((const float4*)(xb + (size_t)c*HWSZ + q4*4));
    }

    int tx = t & 15;        // 4 o
    int ty = t >> 4;        // 8 px (4 pairs)

    for (int k=0;k<9;k++){
        __syncthreads();
        #pragma unroll
        for (int i=t; i<64*16; i+=TPB){
            int c = i>>4, q4 = i&15;
            *(float4*)&B_s[c][q4*4] = *(const float4*)(g_Wt + c*576 + k*64 + q4*4);
        }
        __syncthreads();

        ull acc[4][4];
        #pragma unroll
        for (int j=0;j<4;j++){ acc[j][0]=0ull; acc[j][1]=0ull; acc[j][2]=0ull; acc[j][3]=0ull; }

        #pragma unroll 8
        for (int kk=0; kk<64; kk++){
            ulonglong2 a01 = *(ulonglong2*)&A_s[kk][ty*8];
            ulonglong2 a23 = *(ulonglong2*)&A_s[kk][ty*8+4];
            float4 bv = *(float4*)&B_s[kk][tx*4];
            ull b0 = pk2(bv.x,bv.x), b1 = pk2(bv.y,bv.y);
            ull b2 = pk2(bv.z,bv.z), b3 = pk2(bv.w,bv.w);
            acc[0][0]=f2fma(a01.x,b0,acc[0][0]); acc[0][1]=f2fma(a01.x,b1,acc[0][1]);
            acc[0][2]=f2fma(a01.x,b2,acc[0][2]); acc[0][3]=f2fma(a01.x,b3,acc[0][3]);
            acc[1][0]=f2fma(a01.y,b0,acc[1][0]); acc[1][1]=f2fma(a01.y,b1,acc[1][1]);
            acc[1][2]=f2fma(a01.y,b2,acc[1][2]); acc[1][3]=f2fma(a01.y,b3,acc[1][3]);
            acc[2][0]=f2fma(a23.x,b0,acc[2][0]); acc[2][1]=f2fma(a23.x,b1,acc[2][1]);
            acc[2][2]=f2fma(a23.x,b2,acc[2][2]); acc[2][3]=f2fma(a23.x,b3,acc[2][3]);
            acc[3][0]=f2fma(a23.y,b0,acc[3][0]); acc[3][1]=f2fma(a23.y,b1,acc[3][1]);
            acc[3][2]=f2fma(a23.y,b2,acc[3][2]); acc[3][3]=f2fma(a23.y,b3,acc[3][3]);
        }

        float* Yp = g_Y + ((size_t)k*HWSZ + hw0)*OO;
        #pragma unroll
        for (int j=0;j<4;j++){
            float l0,h0,l1,h1,l2,h2,l3,h3;
            upk2(acc[j][0],l0,h0); upk2(acc[j][1],l1,h1);
            upk2(acc[j][2],l2,h2); upk2(acc[j][3],l3,h3);
            int pxa = ty*8 + 2*j;
            *(float4*)(Yp + (size_t)pxa    *OO + tx*4) = make_float4(l0,l1,l2,l3);
            *(float4*)(Yp + (size_t)(pxa+1)*OO + tx*4) = make_float4(h0,h1,h2,h3);
        }
    }
}

// ---- P3: per-batch gather: out[b,o,hw] = sum_k sum_corner w·Y[k,idx,o] ------
// 128 threads/CTA, warp = 8 px, grid 512 per batch. Y rows hit L2.
__global__ void __launch_bounds__(128)
k_gather(float* __restrict__ out, int b){
    __shared__ __align__(16) float tile[4][64][12];   // [warp][o][px pad12] = 12 KB

    int w   = threadIdx.x >> 5;
    int l   = threadIdx.x & 31;
    int hwb = blockIdx.x*32 + w*8;
    size_t pbase = (size_t)b*HWSZ + hwb;
    const float* Yb = g_Y + 2*l;

    for (int i=0;i<8;i+=2){
        const float4* cwA = &g_cw4[(pbase+i)*9];
        const int4*   ciA = &g_ci4[(pbase+i)*9];
        const float4* cwB = cwA + 9;
        const int4*   ciB = ciA + 9;
        ull a0=0ull, a1=0ull, c0=0ull, c1=0ull;
        #pragma unroll 3
        for (int k=0;k<9;k++){
            float4 wA = __ldg(cwA+k); int4 iA = __ldg(ciA+k);
            float4 wB = __ldg(cwB+k); int4 iB = __ldg(ciB+k);
            const float* Yk = Yb + (size_t)k*HWSZ*OO;
            ull vA0 = ldg2(Yk + (size_t)iA.x*OO);
            ull vA1 = ldg2(Yk + (size_t)iA.y*OO);
            ull vA2 = ldg2(Yk + (size_t)iA.z*OO);
            ull vA3 = ldg2(Yk + (size_t)iA.w*OO);
            ull vB0 = ldg2(Yk + (size_t)iB.x*OO);
            ull vB1 = ldg2(Yk + (size_t)iB.y*OO);
            ull vB2 = ldg2(Yk + (size_t)iB.z*OO);
            ull vB3 = ldg2(Yk + (size_t)iB.w*OO);
            a0 = f2fma(pk2(wA.x,wA.x), vA0, a0);
            a1 = f2fma(pk2(wA.y,wA.y), vA1, a1);
            a0 = f2fma(pk2(wA.z,wA.z), vA2, a0);
            a1 = f2fma(pk2(wA.w,wA.w), vA3, a1);
            c0 = f2fma(pk2(wB.x,wB.x), vB0, c0);
            c1 = f2fma(pk2(wB.y,wB.y), vB1, c1);
            c0 = f2fma(pk2(wB.z,wB.z), vB2, c0);
            c1 = f2fma(pk2(wB.w,wB.w), vB3, c1);
        }
        ull sA = f2add(a0,a1), sB = f2add(c0,c1);
        float lo,hi;
        upk2(sA,lo,hi); tile[w][2*l][i]   = lo; tile[w][2*l+1][i]   = hi;
        upk2(sB,lo,hi); tile[w][2*l][i+1] = lo; tile[w][2*l+1][i+1] = hi;
    }
    __syncwarp();
    #pragma unroll
    for (int rr=0;rr<2;rr++){
        int o = l + rr*32;
        float* op = out + ((size_t)(b*OO + o))*HWSZ + hwb;
        *(float4*)(op)     = *(float4*)&tile[w][o][0];
        *(float4*)(op + 4) = *(float4*)&tile[w][o][4];
    }
}

// ---------------- launch ------------------------------------------------------
extern "C" void kernel_launch(void* const* d_in, const int* in_sizes, int n_in,
                              void* d_out, int out_size){
    const float* x        = (const float*)d_in[0];
    const float* w_main   = (const float*)d_in[1];
    const float* w_offset = (const float*)d_in[2];
    const float* b_offset = (const float*)d_in[3];
    const float* w_mask   = (const float*)d_in[4];
    const float* b_mask   = (const float*)d_in[5];
    float* out = (float*)d_out;

    int prep_n = CC*576 + CC*9*28;
    k_prep<<<(prep_n + TPB-1)/TPB, TPB>>>(w_main, w_offset, w_mask);
    k_offmask<<<NPIX/TPB, TPB>>>(x, b_offset, b_mask);
    for (int b=0;b<BB;b++){
        k_gemm  <<<HWSZ/128, TPB>>>(x, b);
        k_gather<<<HWSZ/32, 128>>>(out, b);
    }
}

// round 7
// speedup vs baseline: 1.7075x; 1.4709x over previous
#include <cuda_runtime.h>
#include <math.h>

#define BB 8
#define CC 64
#define OO 64
#define HH 128
#define WW 128
#define HWSZ (HH*WW)            // 16384
#define NPIX (BB*HWSZ)          // 131072
#define TPB 256

typedef unsigned long long ull;

// ---------------- scratch (allocation-free: __device__ globals) --------------
__device__ float  g_wom_t[CC*9*28];            // [c][t][j] j:0..17 offset,18..26 mask,27 pad
__device__ float  g_Wt[CC*576];                // [c][k*64+o]
__device__ float4 g_cw4[(size_t)NPIX*9];       // per (p,k): 4 corner weights (mask folded)
__device__ int4   g_ci4[(size_t)NPIX*9];       // per (p,k): 4 clamped hw indices
__device__ float  g_xt[(size_t)NPIX*CC];       // x transposed: [b][hw][c]  (33.5 MB, L2-resident)
__device__ float  g_S[(size_t)576*NPIX];       // sampled: [k*64+c][p]  (302 MB)

// ---------------- packed f32x2 helpers ---------------------------------------
__device__ __forceinline__ ull pk2(float lo, float hi){
    ull r; asm("mov.b64 %0, {%1,%2};" : "=l"(r) : "f"(lo), "f"(hi)); return r;
}
__device__ __forceinline__ void upk2(ull v, float& lo, float& hi){
    asm("mov.b64 {%0,%1}, %2;" : "=f"(lo), "=f"(hi) : "l"(v));
}
__device__ __forceinline__ ull f2fma(ull a, ull b, ull c){
    ull d; asm("fma.rn.f32x2 %0, %1, %2, %3;" : "=l"(d) : "l"(a), "l"(b), "l"(c)); return d;
}
__device__ __forceinline__ ull ldg2(const float* p){
    ull v; asm("ld.global.nc.b64 %0, [%1];" : "=l"(v) : "l"(p)); return v;
}

// ---------------- prep: transpose weights ------------------------------------
__global__ void k_prep(const float* __restrict__ wm,
                       const float* __restrict__ wo,
                       const float* __restrict__ wk){
    int i = blockIdx.x*TPB + threadIdx.x;
    if (i < CC*576){                       // g_Wt[c][k*64+o] = wm[o,c,k]
        int c = i/576; int r = i - c*576; int k = r/64; int o = r - k*64;
        g_Wt[i] = wm[(o*CC + c)*9 + k];
    }
    int j2 = i - CC*576;
    if (j2 >= 0 && j2 < CC*9*28){
        int ct = j2/28; int j = j2 - ct*28; int c = ct/9; int t = ct - c*9;
        float v = 0.f;
        if (j < 18)      v = wo[(j*CC + c)*9 + t];
        else if (j < 27) v = wk[((j-18)*CC + c)*9 + t];
        g_wom_t[j2] = v;
    }
}

// ---------------- P0: x [b][c][hw] -> g_xt [b][hw][c] -------------------------
__global__ void k_xt(const float* __restrict__ x){
    __shared__ float t[32][33];
    int b  = blockIdx.z;
    int c0 = blockIdx.y*32;
    int hw0= blockIdx.x*32;
    const float* xb = x + ((size_t)b*CC + c0)*HWSZ + hw0;
    for (int i = threadIdx.y; i < 32; i += 8)
        t[i][threadIdx.x] = xb[(size_t)i*HWSZ + threadIdx.x];   // t[c][hw]
    __syncthreads();
    float* xtb = g_xt + ((size_t)b*HWSZ + hw0)*CC + c0;
    for (int i = threadIdx.y; i < 32; i += 8)
        xtb[(size_t)i*CC + threadIdx.x] = t[threadIdx.x][i];    // [hw][c]
}

// ---- P1: offset(18)+mask(9) 3x3 conv, fused; emit folded corner wgts/idx ----
__global__ void __launch_bounds__(TPB)
k_offmask(const float* __restrict__ x,
          const float* __restrict__ boff,
          const float* __restrict__ bmsk){
    __shared__ __align__(16) float s_wom[32*9*28];   // 31.5 KB

    int p   = blockIdx.x*TPB + threadIdx.x;
    int b   = p >> 14;
    int hw  = p & (HWSZ-1);
    int h   = hw >> 7;
    int wp  = hw & (WW-1);
    const float* xb = x + (size_t)b*CC*HWSZ;

    ull acc[14];
    #pragma unroll
    for (int q=0;q<14;q++){
        int j0=2*q, j1=2*q+1;
        float lo = (j0<18)? boff[j0] : (j0<27 ? bmsk[j0-18] : 0.f);
        float hi = (j1<18)? boff[j1] : (j1<27 ? bmsk[j1-18] : 0.f);
        acc[q] = pk2(lo,hi);
    }

    for (int cc=0; cc<CC; cc+=32){
        __syncthreads();
        for (int i=threadIdx.x; i<32*9*28; i+=TPB)
            s_wom[i] = g_wom_t[cc*9*28 + i];
        __syncthreads();

        for (int c=0;c<32;c++){
            const float* xc = xb + (cc+c)*HWSZ;
            float v[9];
            #pragma unroll
            for (int t=0;t<9;t++){
                int yy = h + t/3 - 1, xx = wp + t%3 - 1;
                v[t] = (yy>=0 && yy<HH && xx>=0 && xx<WW) ? __ldg(xc + yy*WW + xx) : 0.f;
            }
            #pragma unroll
            for (int t=0;t<9;t++){
                ull vv = pk2(v[t], v[t]);
                const ulonglong2* wq = (const ulonglong2*)&s_wom[(c*9+t)*28];
                #pragma unroll
                for (int q=0;q<7;q++){
                    ulonglong2 ww = wq[q];
                    acc[2*q]   = f2fma(vv, ww.x, acc[2*q]);
                    acc[2*q+1] = f2fma(vv, ww.y, acc[2*q+1]);
                }
            }
        }
    }

    #pragma unroll
    for (int k=0;k<9;k++){
        float dy, dx; upk2(acc[k], dy, dx);
        float mlo, mhi; upk2(acc[9 + k/2], mlo, mhi);
        float mraw = (k & 1) ? mhi : mlo;
        float mk = 1.f/(1.f + expf(-mraw));

        float py = dy + (float)(h + k/3 - 1);
        float px = dx + (float)(wp + k%3 - 1);
        float y0f = floorf(py), x0f = floorf(px);
        float ly = py - y0f, lx = px - x0f;
        int y0 = (int)y0f, x0 = (int)x0f;
        int y1 = y0 + 1,   x1 = x0 + 1;

        float vy0 = (y0>=0 && y0<HH) ? 1.f : 0.f;
        float vy1 = (y1>=0 && y1<HH) ? 1.f : 0.f;
        float vx0 = (x0>=0 && x0<WW) ? 1.f : 0.f;
        float vx1 = (x1>=0 && x1<WW) ? 1.f : 0.f;

        float w00 = (1.f-ly)*(1.f-lx)*vy0*vx0*mk;
        float w01 = (1.f-ly)*lx      *vy0*vx1*mk;
        float w10 = ly      *(1.f-lx)*vy1*vx0*mk;
        float w11 = ly      *lx      *vy1*vx1*mk;

        int y0c = min(max(y0,0),HH-1), y1c = min(max(y1,0),HH-1);
        int x0c = min(max(x0,0),WW-1), x1c = min(max(x1,0),WW-1);

        g_cw4[(size_t)p*9 + k] = make_float4(w00,w01,w10,w11);
        g_ci4[(size_t)p*9 + k] = make_int4(y0c*WW+x0c, y0c*WW+x1c,
                                           y1c*WW+x0c, y1c*WW+x1c);
    }
}

// ---- P2: sample: S[k*64+c][p] = sum_corner w(p,k) * x_t[idx][c] -------------
// CTA = 32 px; warp gathers 4 px (all 32 lanes read same 256B x_t rows — L2 hits),
// stages [c][px] tile in smem, writes S coalesced.
__global__ void __launch_bounds__(TPB)
k_sample(){
    __shared__ float tile[64][33];   // 8.4 KB

    int t  = threadIdx.x, w = t>>5, l = t&31;
    int p0 = blockIdx.x*32;
    int b  = p0 >> 14;
    const float* xtb = g_xt + (size_t)b*HWSZ*CC;

    for (int k=0;k<9;k++){
        __syncthreads();
        #pragma unroll
        for (int j=0;j<4;j++){
            int px = w*4 + j;
            size_t pk = (size_t)(p0+px)*9 + k;
            float4 wq = __ldg(&g_cw4[pk]);
            int4   iq = __ldg(&g_ci4[pk]);
            ull v;
            v = f2fma(pk2(wq.x,wq.x), ldg2(xtb + (size_t)iq.x*CC + 2*l), 0ull);
            v = f2fma(pk2(wq.y,wq.y), ldg2(xtb + (size_t)iq.y*CC + 2*l), v);
            v = f2fma(pk2(wq.z,wq.z), ldg2(xtb + (size_t)iq.z*CC + 2*l), v);
            v = f2fma(pk2(wq.w,wq.w), ldg2(xtb + (size_t)iq.w*CC + 2*l), v);
            float lo,hi; upk2(v,lo,hi);
            tile[2*l  ][px] = lo;
            tile[2*l+1][px] = hi;
        }
        __syncthreads();
        float* Sk = g_S + ((size_t)k*64)*NPIX + p0;
        #pragma unroll
        for (int j=0;j<8;j++){
            int c = w*8 + j;
            Sk[(size_t)c*NPIX + l] = tile[c][l];     // 128B coalesced per row
        }
    }
}

// ---- P3: streaming GEMM  out[p,o] = sum_{k,c} S[k*64+c][p] * Wt[c][k*64+o] --
// CTA = 128 px, K=576 in 9 chunks of 64; acc persists in regs; next A/B chunk
// prefetched to registers during compute.
__global__ void __launch_bounds__(TPB)
k_gemm2(float* __restrict__ out){
    __shared__ __align__(16) float sm[64*128 + 64*64];   // 48 KB
    float* A_s = sm;           // [c][128]
    float* B_s = sm + 8192;    // [c][64]

    int t   = threadIdx.x;
    int p0  = blockIdx.x*128;
    int b   = p0 >> 14;
    int hw0 = p0 & (HWSZ-1);

    // initial A(0), B(0)
    #pragma unroll
    for (int q=0;q<8;q++){
        int fi = q*256+t; int c = fi>>5, x4 = fi&31;
        *(float4*)&A_s[c*128 + x4*4] =
            __ldg((const float4*)(g_S + (size_t)c*NPIX + p0 + x4*4));
    }
    #pragma unroll
    for (int q=0;q<4;q++){
        int fb = q*256+t; int c = fb>>4, o4 = fb&15;
        *(float4*)&B_s[c*64 + o4*4] = *(const float4*)(g_Wt + c*576 + o4*4);
    }
    __syncthreads();

    int tx = t & 15;     // 4 o  : o = tx*4+q
    int ty = t >> 4;     // 8 px : px pairs ty*8+2j
    ull acc[4][4];
    #pragma unroll
    for (int j=0;j<4;j++){ acc[j][0]=0ull; acc[j][1]=0ull; acc[j][2]=0ull; acc[j][3]=0ull; }

    for (int kc=0;kc<9;kc++){
        float4 pfA[8]; float4 pfB[4];
        if (kc < 8){
            #pragma unroll
            for (int q=0;q<8;q++){
                int fi = q*256+t; int c = fi>>5, x4 = fi&31;
                pfA[q] = __ldg((const float4*)(g_S + ((size_t)((kc+1)*64+c))*NPIX + p0 + x4*4));
            }
            #pragma unroll
            for (int q=0;q<4;q++){
                int fb = q*256+t; int c = fb>>4, o4 = fb&15;
                pfB[q] = *(const float4*)(g_Wt + c*576 + (kc+1)*64 + o4*4);
            }
        }

        #pragma unroll 8
        for (int kk=0; kk<64; kk++){
            ulonglong2 a01 = *(ulonglong2*)&A_s[kk*128 + ty*8];
            ulonglong2 a23 = *(ulonglong2*)&A_s[kk*128 + ty*8+4];
            float4 bv = *(float4*)&B_s[kk*64 + tx*4];
            ull b0 = pk2(bv.x,bv.x), b1 = pk2(bv.y,bv.y);
            ull b2 = pk2(bv.z,bv.z), b3 = pk2(bv.w,bv.w);
            acc[0][0]=f2fma(a01.x,b0,acc[0][0]); acc[0][1]=f2fma(a01.x,b1,acc[0][1]);
            acc[0][2]=f2fma(a01.x,b2,acc[0][2]); acc[0][3]=f2fma(a01.x,b3,acc[0][3]);
            acc[1][0]=f2fma(a01.y,b0,acc[1][0]); acc[1][1]=f2fma(a01.y,b1,acc[1][1]);
            acc[1][2]=f2fma(a01.y,b2,acc[1][2]); acc[1][3]=f2fma(a01.y,b3,acc[1][3]);
            acc[2][0]=f2fma(a23.x,b0,acc[2][0]); acc[2][1]=f2fma(a23.x,b1,acc[2][1]);
            acc[2][2]=f2fma(a23.x,b2,acc[2][2]); acc[2][3]=f2fma(a23.x,b3,acc[2][3]);
            acc[3][0]=f2fma(a23.y,b0,acc[3][0]); acc[3][1]=f2fma(a23.y,b1,acc[3][1]);
            acc[3][2]=f2fma(a23.y,b2,acc[3][2]); acc[3][3]=f2fma(a23.y,b3,acc[3][3]);
        }

        if (kc < 8){
            __syncthreads();
            #pragma unroll
            for (int q=0;q<8;q++){
                int fi = q*256+t; int c = fi>>5, x4 = fi&31;
                *(float4*)&A_s[c*128 + x4*4] = pfA[q];
            }
            #pragma unroll
            for (int q=0;q<4;q++){
                int fb = q*256+t; int c = fb>>4, o4 = fb&15;
                *(float4*)&B_s[c*64 + o4*4] = pfB[q];
            }
            __syncthreads();
        }
    }

    // epilogue: transpose to [px][o] in smem, then coalesced stores per o row
    __syncthreads();
    #pragma unroll
    for (int j=0;j<4;j++){
        #pragma unroll
        for (int q=0;q<4;q++){
            float lo,hi; upk2(acc[j][q],lo,hi);
            int o = tx*4+q, px = ty*8+2*j;
            sm[(size_t)px*65 + o]     = lo;
            sm[(size_t)(px+1)*65 + o] = hi;
        }
    }
    __syncthreads();
    {
        int w = t>>5, l = t&31;
        #pragma unroll
        for (int rr=0;rr<8;rr++){
            int o = w*8 + rr;
            float* op = out + ((size_t)(b*OO+o))*HWSZ + hw0;
            #pragma unroll
            for (int seg=0;seg<4;seg++){
                int px = seg*32 + l;
                op[px] = sm[(size_t)px*65 + o];
            }
        }
    }
}

// ---------------- launch ------------------------------------------------------
extern "C" void kernel_launch(void* const* d_in, const int* in_sizes, int n_in,
                              void* d_out, int out_size){
    const float* x        = (const float*)d_in[0];
    const float* w_main   = (const float*)d_in[1];
    const float* w_offset = (const float*)d_in[2];
    const float* b_offset = (const float*)d_in[3];
    const float* w_mask   = (const float*)d_in[4];
    const float* b_mask   = (const float*)d_in[5];
    float* out = (float*)d_out;

    int prep_n = CC*576 + CC*9*28;
    k_prep<<<(prep_n + TPB-1)/TPB, TPB>>>(w_main, w_offset, w_mask);
    dim3 gx(HWSZ/32, CC/32, BB);
    k_xt<<<gx, dim3(32,8)>>>(x);
    k_offmask<<<NPIX/TPB, TPB>>>(x, b_offset, b_mask);
    k_sample<<<NPIX/32, TPB>>>();
    k_gemm2<<<NPIX/128, TPB>>>(out);
}